// round 16
// baseline (speedup 1.0000x reference)
#include <cuda_runtime.h>
#include <math.h>

// C222 sign convention (verified R6): C[2][2][2] > 0.
#define C62_SIGN (+1.0)

// ---- packed weight layout (floats) ----
#define OFF_W000S 0        /* 136*32 */
#define OFF_W110S 4352     /* 45*32  */
#define OFF_W011C 5792     /* 144*32 (w011 + w101^T folded) */
#define OFF_W111S 10400    /* 45*32  */
#define OFF_V110T 11840    /* 32*32  */
#define OFF_VSUM  12864    /* 32*32  */
#define OFF_C     13888    /* 125 pad 128 */
#define WTOT      14016
#define OFF_PAIRS 14016    /* 48 ints */
#define SCRBASE   14064

// ---- per-warp-per-element scratch (floats), liveness-aliased ----
// timeline: ROW(load..u2) U1(u1..u2) G(gram..h0) U2(u2..term3)
//           H2(publish..end)@0  H0(publish..vsum)@288  A(aloop..end)@328
#define U1b   328          /* 225 pad 228 */
#define Gb    556          /* 45, dead before U2 written */
#define U2b   556          /* 45*8 = 360, ends 916 */
#define H2b   0            /* 32*8 = 256 (ROW region dead after u2) */
#define H0b   288          /* 32 */
#define Ab    328          /* 32*8 = 256 (U1 region dead after u2) */
#define SCR_  920

#define NWARPS   12
#define NTHREADS 384
#define SMEM_FLOATS (SCRBASE + NWARPS * 3 * SCR_)
#define SMEM_BYTES  (SMEM_FLOATS * 4)

__device__ float gPack[WTOT];

// =======================================================================
// prep_fold: C222 closed-form (block 0) + fold/symmetrize weights (all)
// =======================================================================
__device__ __forceinline__ void tri_decode(int p, int N, int& u, int& v) {
    int uu = 0, rem = p;
    while (rem >= N - uu) { rem -= N - uu; uu++; }
    u = uu; v = uu + rem;
}

__global__ void prep_fold_kernel(const float* __restrict__ w000, const float* __restrict__ w110,
                                 const float* __restrict__ w011, const float* __restrict__ w101,
                                 const float* __restrict__ w111, const float* __restrict__ v010,
                                 const float* __restrict__ v100, const float* __restrict__ v110)
{
    // ---- block 0: compute C tensor (125 threads) ----
    if (blockIdx.x == 0) {
        __shared__ double sc[125];
        __shared__ double sscale;
        int tid = threadIdx.x;
        if (tid < 125) {
            const double r3 = rsqrt(3.0);
            const double S[5][9] = {
                {0,1,0, 1,0,0, 0,0,0},                 // xy
                {0,0,0, 0,0,1, 0,1,0},                 // yz
                {-r3,0,0, 0,-r3,0, 0,0,2.0*r3},        // (3z^2-r^2)/sqrt3
                {0,0,1, 0,0,0, 1,0,0},                 // xz
                {1,0,0, 0,-1,0, 0,0,0}                 // x^2-y^2
            };
            int a = tid / 25, b = (tid / 5) % 5, c = tid % 5;
            double M[9];
            for (int i = 0; i < 3; i++)
                for (int j = 0; j < 3; j++) {
                    double acc = 0.0;
                    for (int k = 0; k < 3; k++) acc += S[a][i*3+k] * S[b][k*3+j];
                    M[i*3+j] = acc;
                }
            double tr = 0.0;
            for (int i = 0; i < 3; i++)
                for (int k = 0; k < 3; k++) tr += M[i*3+k] * S[c][k*3+i];
            sc[tid] = tr;
        }
        __syncthreads();
        if (tid == 0) {
            double n2 = 0.0;
            for (int i = 0; i < 125; i++) n2 += sc[i]*sc[i];
            double sgn = (sc[62] * C62_SIGN > 0.0) ? 1.0 : -1.0;
            sscale = sgn / sqrt(n2);
        }
        __syncthreads();
        if (tid < 125) gPack[OFF_C + tid] = (float)(sc[tid] * sscale);
        if (tid >= 125 && tid < 128) gPack[OFF_C + tid] = 0.f;
    }

    // ---- all blocks: weight folding (grid-stride) ----
    const float c0 = (float)(1.0 / sqrt(337.0));
    const float c2 = (float)sqrt(5.0 / 369.0);
    const float dd = (float)sqrt(5.0 / 3072.0);
    const float i5 = (float)(1.0 / sqrt(5.0));

    int stride = gridDim.x * blockDim.x;
    int t0 = blockIdx.x * blockDim.x + threadIdx.x;

    for (int idx = t0; idx < 136*32; idx += stride) {
        int p = idx >> 5, w = idx & 31, u, v;
        tri_decode(p, 16, u, v);
        float val = (u == v) ? w000[(u*16+u)*32 + w]
                             : (w000[(u*16+v)*32 + w] + w000[(v*16+u)*32 + w]);
        gPack[OFF_W000S + idx] = c0 * val;
    }
    for (int idx = t0; idx < 45*32; idx += stride) {
        int p = idx >> 5, w = idx & 31, u, v;
        tri_decode(p, 9, u, v);
        float v1 = (u == v) ? w110[(u*9+u)*32 + w]
                            : (w110[(u*9+v)*32 + w] + w110[(v*9+u)*32 + w]);
        gPack[OFF_W110S + idx] = (c0 * i5) * v1;
        float v2 = (u == v) ? w111[(u*9+u)*32 + w]
                            : (w111[(u*9+v)*32 + w] + w111[(v*9+u)*32 + w]);
        gPack[OFF_W111S + idx] = c2 * v2;
    }
    for (int idx = t0; idx < 144*32; idx += stride) {
        int r = idx >> 5, w = idx & 31;
        int u = r / 9, t9 = r - u * 9;
        gPack[OFF_W011C + idx] = (c2 * i5) * (w011[idx] + w101[(t9*16 + u)*32 + w]);
    }
    for (int idx = t0; idx < 1024; idx += stride) {
        int u = idx >> 5, v = idx & 31;
        gPack[OFF_V110T + v*32 + u] = dd * v110[idx];
        gPack[OFF_VSUM  + idx]      = (dd * i5) * (v010[idx] + v100[v*32 + u]);
    }
}

// =======================================================================
// main: warp per 3 elements, H=32 -> lanes, weights amortized 3x
// =======================================================================
__global__ void __launch_bounds__(NTHREADS, 1)
eq_head_kernel(const float* __restrict__ scalars, const float* __restrict__ kt,
               float* __restrict__ outp, int NB, int NK)
{
    extern __shared__ float sm[];
    for (int i = threadIdx.x; i < WTOT; i += NTHREADS) sm[i] = gPack[i];
    int* sPairs = (int*)(sm + OFF_PAIRS);
    if (threadIdx.x < 48) {
        int p = threadIdx.x, val = 0;
        if (p < 45) {
            const int RT[9] = {0, 8, 16, 32, 192, 208, 280, 304, 320};
            int u = 0, acc = 0;
            while (acc + (9 - u) <= p) { acc += 9 - u; u++; }
            int v = u + (p - acc);
            val = (u * 25) | (RT[u] << 8) | (RT[v] << 20);
        }
        sPairs[p] = val;
    }
    __syncthreads();

    const float* sW000S = sm + OFF_W000S;
    const float* sW110S = sm + OFF_W110S;
    const float* sW011C = sm + OFF_W011C;
    const float* sW111S = sm + OFF_W111S;
    const float* sV110T = sm + OFF_V110T;
    const float* sVSUM  = sm + OFF_VSUM;
    const float* sCt    = sm + OFF_C;

    const int lane = threadIdx.x & 31;
    const int warp = threadIdx.x >> 5;
    float* scr0 = sm + SCRBASE + warp * (3 * SCR_);
    float* scr1 = scr0 + SCR_;
    float* scr2 = scr1 + SCR_;

    const int gw = blockIdx.x * NWARPS + warp;
    const int TW = gridDim.x * NWARPS;
    const int RN = NK * 5;
    const int ROW8[9] = {0, 8, 16, 32, 192, 208, 280, 304, 320};
    const int pl = lane / 5, kk = lane - pl * 5;

    for (int e = gw * 3; e < NB; e += TW * 3) {
        const int e0 = e;
        const int e1 = (e + 1 < NB) ? (e + 1) : e;
        const int e2 = (e + 2 < NB) ? (e + 2) : e;
        const bool has1 = (e + 1 < NB);
        const bool has2 = (e + 2 < NB);

        // ---- load kt rows (R8 layout) for all three ----
        const float* ke0 = kt + (size_t)e0 * RN;
        const float* ke1 = kt + (size_t)e1 * RN;
        const float* ke2 = kt + (size_t)e2 * RN;
        for (int m = lane; m < RN; m += 32) {
            int n = m / 5, i = m - n * 5;
            scr0[n * 8 + i] = __ldg(ke0 + m);
            scr1[n * 8 + i] = __ldg(ke1 + m);
            scr2[n * 8 + i] = __ldg(ke2 + m);
        }
        // ---- scalars to regs ----
        float s0_[16], s1_[16], s2_[16];
        {
            const float4* p0 = (const float4*)(scalars + (size_t)e0 * 16);
            const float4* p1 = (const float4*)(scalars + (size_t)e1 * 16);
            const float4* p2 = (const float4*)(scalars + (size_t)e2 * 16);
            #pragma unroll
            for (int q = 0; q < 4; q++) {
                float4 a = __ldg(p0 + q), b = __ldg(p1 + q), c = __ldg(p2 + q);
                s0_[q*4+0]=a.x; s0_[q*4+1]=a.y; s0_[q*4+2]=a.z; s0_[q*4+3]=a.w;
                s1_[q*4+0]=b.x; s1_[q*4+1]=b.y; s1_[q*4+2]=b.z; s1_[q*4+3]=b.w;
                s2_[q*4+0]=c.x; s2_[q*4+1]=c.y; s2_[q*4+2]=c.z; s2_[q*4+3]=c.w;
            }
        }
        __syncwarp();

        // ---- kernel-sum rows (tri-lane: 0-4 e0, 8-12 e1, 16-20 e2) ----
        {
            int li = lane & 7;
            int grp = lane >> 3;
            float* sc = (grp == 0) ? scr0 : (grp == 1) ? scr1 : scr2;
            if (li < 5 && grp < 3) {
                float a = 0.f;
                for (int n = 0; n < NK; n++) a += sc[n * 8 + li];
                sc[320 + li] = a;
            }
        }
        __syncwarp();

        // ---- Gram g[p] -> Gb (all three) ----
        #pragma unroll
        for (int r = 0; r < 2; r++) {
            int p = lane + 32 * r;
            if (p < 45) {
                int t3 = sPairs[p];
                int ru = (t3 >> 8) & 0xFFF, rv = t3 >> 20;
                float g0 = 0.f, g1 = 0.f, g2 = 0.f;
                #pragma unroll
                for (int i = 0; i < 5; i++) {
                    g0 = fmaf(scr0[ru + i], scr0[rv + i], g0);
                    g1 = fmaf(scr1[ru + i], scr1[rv + i], g1);
                    g2 = fmaf(scr2[ru + i], scr2[rv + i], g2);
                }
                scr0[Gb + p] = g0;
                scr1[Gb + p] = g1;
                scr2[Gb + p] = g2;
            }
        }

        // ---- h0: w000S part ----
        float h0a = 0.f, h0b = 0.f, h0c = 0.f;
        {
            int p = 0;
            #pragma unroll
            for (int u = 0; u < 16; u++) {
                #pragma unroll
                for (int v = u; v < 16; v++) {
                    float w = sW000S[p*32 + lane];
                    h0a = fmaf(w, s0_[u]*s0_[v], h0a);
                    h0b = fmaf(w, s1_[u]*s1_[v], h0b);
                    h0c = fmaf(w, s2_[u]*s2_[v], h0c);
                    p++;
                }
            }
        }
        __syncwarp();
        #pragma unroll
        for (int p = 0; p < 45; p++) {
            float w = sW110S[p*32 + lane];
            h0a = fmaf(w, scr0[Gb + p], h0a);
            h0b = fmaf(w, scr1[Gb + p], h0b);
            h0c = fmaf(w, scr2[Gb + p], h0c);
        }

        // ---- h2 terms 1+2: folded (w011+w101^T).s times t[k] ----
        float A0=0.f,A1=0.f,A2=0.f,A3=0.f,A4=0.f;
        float B0=0.f,B1=0.f,B2=0.f,B3=0.f,B4=0.f;
        float E0=0.f,E1=0.f,E2=0.f,E3=0.f,E4=0.f;
        #pragma unroll
        for (int t9 = 0; t9 < 9; t9++) {
            const int ro = ROW8[t9];
            float4 ta = *(const float4*)(scr0 + ro);
            float  taw = scr0[ro + 4];
            float4 tb = *(const float4*)(scr1 + ro);
            float  tbw = scr1[ro + 4];
            float4 tc = *(const float4*)(scr2 + ro);
            float  tcw = scr2[ro + 4];
            float ca = 0.f, cb = 0.f, cc = 0.f;
            #pragma unroll
            for (int u = 0; u < 16; u++) {
                float w = sW011C[(u*9 + t9)*32 + lane];
                ca = fmaf(w, s0_[u], ca);
                cb = fmaf(w, s1_[u], cb);
                cc = fmaf(w, s2_[u], cc);
            }
            A0 = fmaf(ca, ta.x, A0); A1 = fmaf(ca, ta.y, A1);
            A2 = fmaf(ca, ta.z, A2); A3 = fmaf(ca, ta.w, A3);
            A4 = fmaf(ca, taw,  A4);
            B0 = fmaf(cb, tb.x, B0); B1 = fmaf(cb, tb.y, B1);
            B2 = fmaf(cb, tb.z, B2); B3 = fmaf(cb, tb.w, B3);
            B4 = fmaf(cb, tbw,  B4);
            E0 = fmaf(cc, tc.x, E0); E1 = fmaf(cc, tc.y, E1);
            E2 = fmaf(cc, tc.z, E2); E3 = fmaf(cc, tc.w, E3);
            E4 = fmaf(cc, tcw,  E4);
        }

        // ---- u1[u][jk] = sum_i t_u[i] C[i*25+jk] (lanes 0..24) ----
        if (lane < 25) {
            float c0v = sCt[lane], c1v = sCt[25 + lane], c2v = sCt[50 + lane],
                  c3v = sCt[75 + lane], c4v = sCt[100 + lane];
            #pragma unroll
            for (int u = 0; u < 9; u++) {
                const int ro = ROW8[u];
                float4 ta = *(const float4*)(scr0 + ro);
                float  taw = scr0[ro + 4];
                scr0[U1b + u*25 + lane] = ta.x*c0v + ta.y*c1v + ta.z*c2v + ta.w*c3v + taw*c4v;
                float4 tb = *(const float4*)(scr1 + ro);
                float  tbw = scr1[ro + 4];
                scr1[U1b + u*25 + lane] = tb.x*c0v + tb.y*c1v + tb.z*c2v + tb.w*c3v + tbw*c4v;
                float4 tc = *(const float4*)(scr2 + ro);
                float  tcw = scr2[ro + 4];
                scr2[U1b + u*25 + lane] = tc.x*c0v + tc.y*c1v + tc.z*c2v + tc.w*c3v + tcw*c4v;
            }
        }
        __syncwarp();

        // ---- u2[p][k] = sum_j u1[u][j*5+k] * t_v[j] ----
        #pragma unroll
        for (int r = 0; r < 8; r++) {
            int p = r * 6 + pl;
            if (lane < 30 && p < 45) {
                int t3 = sPairs[p];
                int u25 = t3 & 0xFF, rv = t3 >> 20;
                float ua = 0.f, ub = 0.f, uc = 0.f;
                #pragma unroll
                for (int j = 0; j < 5; j++) {
                    ua = fmaf(scr0[U1b + u25 + j*5 + kk], scr0[rv + j], ua);
                    ub = fmaf(scr1[U1b + u25 + j*5 + kk], scr1[rv + j], ub);
                    uc = fmaf(scr2[U1b + u25 + j*5 + kk], scr2[rv + j], uc);
                }
                scr0[U2b + p*8 + kk] = ua;
                scr1[U2b + p*8 + kk] = ub;
                scr2[U2b + p*8 + kk] = uc;
            }
        }
        __syncwarp();

        // ---- h2 term3: sum_p w111S[p][w] * u2[p][k] ----
        #pragma unroll
        for (int p = 0; p < 45; p++) {
            float w = sW111S[p*32 + lane];
            float4 ua = *(const float4*)(scr0 + U2b + p*8);
            float  uaw = scr0[U2b + p*8 + 4];
            A0 = fmaf(w, ua.x, A0); A1 = fmaf(w, ua.y, A1);
            A2 = fmaf(w, ua.z, A2); A3 = fmaf(w, ua.w, A3);
            A4 = fmaf(w, uaw,  A4);
            float4 ub = *(const float4*)(scr1 + U2b + p*8);
            float  ubw = scr1[U2b + p*8 + 4];
            B0 = fmaf(w, ub.x, B0); B1 = fmaf(w, ub.y, B1);
            B2 = fmaf(w, ub.z, B2); B3 = fmaf(w, ub.w, B3);
            B4 = fmaf(w, ubw,  B4);
            float4 uc = *(const float4*)(scr2 + U2b + p*8);
            float  ucw = scr2[U2b + p*8 + 4];
            E0 = fmaf(w, uc.x, E0); E1 = fmaf(w, uc.y, E1);
            E2 = fmaf(w, uc.z, E2); E3 = fmaf(w, uc.w, E3);
            E4 = fmaf(w, ucw,  E4);
        }
        __syncwarp();   // U2/ROW/U1 reads done before H2/A overwrite those regions

        // ---- publish h2, h0 ----
        *(float4*)(scr0 + H2b + lane*8) = make_float4(A0, A1, A2, A3);
        scr0[H2b + lane*8 + 4] = A4;
        scr0[H0b + lane] = h0a;
        *(float4*)(scr1 + H2b + lane*8) = make_float4(B0, B1, B2, B3);
        scr1[H2b + lane*8 + 4] = B4;
        scr1[H0b + lane] = h0b;
        *(float4*)(scr2 + H2b + lane*8) = make_float4(E0, E1, E2, E3);
        scr2[H2b + lane*8 + 4] = E4;
        scr2[H0b + lane] = h0c;
        __syncwarp();

        // ---- a[w][j] = sum_v v110T[v][w] h2[v][j] ----
        {
            float a0=0.f,a1=0.f,a2=0.f,a3=0.f,a4=0.f;
            float b0=0.f,b1=0.f,b2v=0.f,b3=0.f,b4=0.f;
            float c0r=0.f,c1r=0.f,c2r=0.f,c3r=0.f,c4r=0.f;
            #pragma unroll
            for (int v = 0; v < 32; v++) {
                float w = sV110T[v*32 + lane];
                float4 ha = *(const float4*)(scr0 + H2b + v*8);
                float  haw = scr0[H2b + v*8 + 4];
                a0 = fmaf(w, ha.x, a0); a1 = fmaf(w, ha.y, a1);
                a2 = fmaf(w, ha.z, a2); a3 = fmaf(w, ha.w, a3);
                a4 = fmaf(w, haw,  a4);
                float4 hb = *(const float4*)(scr1 + H2b + v*8);
                float  hbw = scr1[H2b + v*8 + 4];
                b0 = fmaf(w, hb.x, b0); b1 = fmaf(w, hb.y, b1);
                b2v = fmaf(w, hb.z, b2v); b3 = fmaf(w, hb.w, b3);
                b4 = fmaf(w, hbw,  b4);
                float4 hc = *(const float4*)(scr2 + H2b + v*8);
                float  hcw = scr2[H2b + v*8 + 4];
                c0r = fmaf(w, hc.x, c0r); c1r = fmaf(w, hc.y, c1r);
                c2r = fmaf(w, hc.z, c2r); c3r = fmaf(w, hc.w, c3r);
                c4r = fmaf(w, hcw,  c4r);
            }
            *(float4*)(scr0 + Ab + lane*8) = make_float4(a0, a1, a2, a3);
            scr0[Ab + lane*8 + 4] = a4;
            *(float4*)(scr1 + Ab + lane*8) = make_float4(b0, b1, b2v, b3);
            scr1[Ab + lane*8 + 4] = b4;
            *(float4*)(scr2 + Ab + lane*8) = make_float4(c0r, c1r, c2r, c3r);
            scr2[Ab + lane*8 + 4] = c4r;
        }

        // ---- r[w] = sum_m VSUM[m][w] * h0[m] ----
        float ra = 0.f, rb = 0.f, rc = 0.f;
        #pragma unroll
        for (int m = 0; m < 32; m++) {
            float w = sVSUM[m*32 + lane];
            ra = fmaf(w, scr0[H0b + m], ra);
            rb = fmaf(w, scr1[H0b + m], rb);
            rc = fmaf(w, scr2[H0b + m], rc);
        }
        __syncwarp();

        // ---- final e0 ----
        {
            float vk0 = ra*A0, vk1 = ra*A1, vk2 = ra*A2, vk3 = ra*A3, vk4 = ra*A4;
            if (lane < 25) {
                float b2 = 0.f;
                #pragma unroll
                for (int u = 0; u < 32; u++)
                    b2 = fmaf(scr0[H2b + u*8 + pl], scr0[Ab + u*8 + kk], b2);
                vk0 = fmaf(b2, sCt[lane*5 + 0], vk0);
                vk1 = fmaf(b2, sCt[lane*5 + 1], vk1);
                vk2 = fmaf(b2, sCt[lane*5 + 2], vk2);
                vk3 = fmaf(b2, sCt[lane*5 + 3], vk3);
                vk4 = fmaf(b2, sCt[lane*5 + 4], vk4);
            }
            #pragma unroll
            for (int off = 16; off > 0; off >>= 1) {
                vk0 += __shfl_xor_sync(0xffffffffu, vk0, off);
                vk1 += __shfl_xor_sync(0xffffffffu, vk1, off);
                vk2 += __shfl_xor_sync(0xffffffffu, vk2, off);
                vk3 += __shfl_xor_sync(0xffffffffu, vk3, off);
                vk4 += __shfl_xor_sync(0xffffffffu, vk4, off);
            }
            if (lane == 0) {
                float* o = outp + (size_t)e0 * 5;
                o[0] = vk0; o[1] = vk1; o[2] = vk2; o[3] = vk3; o[4] = vk4;
            }
        }
        // ---- final e1 ----
        {
            float vk0 = rb*B0, vk1 = rb*B1, vk2 = rb*B2, vk3 = rb*B3, vk4 = rb*B4;
            if (lane < 25) {
                float b2 = 0.f;
                #pragma unroll
                for (int u = 0; u < 32; u++)
                    b2 = fmaf(scr1[H2b + u*8 + pl], scr1[Ab + u*8 + kk], b2);
                vk0 = fmaf(b2, sCt[lane*5 + 0], vk0);
                vk1 = fmaf(b2, sCt[lane*5 + 1], vk1);
                vk2 = fmaf(b2, sCt[lane*5 + 2], vk2);
                vk3 = fmaf(b2, sCt[lane*5 + 3], vk3);
                vk4 = fmaf(b2, sCt[lane*5 + 4], vk4);
            }
            #pragma unroll
            for (int off = 16; off > 0; off >>= 1) {
                vk0 += __shfl_xor_sync(0xffffffffu, vk0, off);
                vk1 += __shfl_xor_sync(0xffffffffu, vk1, off);
                vk2 += __shfl_xor_sync(0xffffffffu, vk2, off);
                vk3 += __shfl_xor_sync(0xffffffffu, vk3, off);
                vk4 += __shfl_xor_sync(0xffffffffu, vk4, off);
            }
            if (lane == 0 && has1) {
                float* o = outp + (size_t)e1 * 5;
                o[0] = vk0; o[1] = vk1; o[2] = vk2; o[3] = vk3; o[4] = vk4;
            }
        }
        // ---- final e2 ----
        {
            float vk0 = rc*E0, vk1 = rc*E1, vk2 = rc*E2, vk3 = rc*E3, vk4 = rc*E4;
            if (lane < 25) {
                float b2 = 0.f;
                #pragma unroll
                for (int u = 0; u < 32; u++)
                    b2 = fmaf(scr2[H2b + u*8 + pl], scr2[Ab + u*8 + kk], b2);
                vk0 = fmaf(b2, sCt[lane*5 + 0], vk0);
                vk1 = fmaf(b2, sCt[lane*5 + 1], vk1);
                vk2 = fmaf(b2, sCt[lane*5 + 2], vk2);
                vk3 = fmaf(b2, sCt[lane*5 + 3], vk3);
                vk4 = fmaf(b2, sCt[lane*5 + 4], vk4);
            }
            #pragma unroll
            for (int off = 16; off > 0; off >>= 1) {
                vk0 += __shfl_xor_sync(0xffffffffu, vk0, off);
                vk1 += __shfl_xor_sync(0xffffffffu, vk1, off);
                vk2 += __shfl_xor_sync(0xffffffffu, vk2, off);
                vk3 += __shfl_xor_sync(0xffffffffu, vk3, off);
                vk4 += __shfl_xor_sync(0xffffffffu, vk4, off);
            }
            if (lane == 0 && has2) {
                float* o = outp + (size_t)e2 * 5;
                o[0] = vk0; o[1] = vk1; o[2] = vk2; o[3] = vk3; o[4] = vk4;
            }
        }
    }
}

extern "C" void kernel_launch(void* const* d_in, const int* in_sizes, int n_in,
                              void* d_out, int out_size) {
    const float* scalars = (const float*)d_in[0];
    const float* kt      = (const float*)d_in[1];
    const float* w000    = (const float*)d_in[2];
    const float* w110    = (const float*)d_in[3];
    const float* w011    = (const float*)d_in[4];
    const float* w101    = (const float*)d_in[5];
    const float* w111    = (const float*)d_in[6];
    const float* v010    = (const float*)d_in[7];
    const float* v100    = (const float*)d_in[8];
    const float* v110    = (const float*)d_in[9];
    float* out = (float*)d_out;

    int B = in_sizes[0] / 16;
    int NK = (B > 0) ? in_sizes[1] / (B * 5) : 40;

    prep_fold_kernel<<<64, 256>>>(w000, w110, w011, w101, w111, v010, v100, v110);

    cudaFuncSetAttribute(eq_head_kernel, cudaFuncAttributeMaxDynamicSharedMemorySize, SMEM_BYTES);
    eq_head_kernel<<<148, NTHREADS, SMEM_BYTES>>>(scalars, kt, out, B, NK);
}